// round 2
// baseline (speedup 1.0000x reference)
#include <cuda_runtime.h>
#include <math.h>

// Problem constants
#define N_B    2
#define S_LEN  2048
#define T_LEN  2048
#define E_DIM  1024
#define H_NUM  16
#define HD     64
#define M_ROWS (N_B * S_LEN)   // 4096

// Scratch (device globals -> no runtime allocation)
__device__ float g_q [M_ROWS * E_DIM];
__device__ float g_k [M_ROWS * E_DIM];
__device__ float g_v [M_ROWS * E_DIM];
__device__ float g_ao[M_ROWS * E_DIM];

// ---------------------------------------------------------------------------
// GEMM: C[M,1024] = (A[M,1024] @ W[1024,1024] + bias) * scale
// 128x128 block tile, BK=16, 256 threads, 8x8 per-thread tile.
// ---------------------------------------------------------------------------
__global__ __launch_bounds__(256, 2)
void gemm_bias(const float* __restrict__ A, const float* __restrict__ W,
               const float* __restrict__ bias, float* __restrict__ C,
               float scale)
{
    __shared__ float As[16][128];   // transposed A tile: As[k][m]
    __shared__ float Bs[16][128];   // Bs[k][n]

    const int tid = threadIdx.x;
    const int tx  = tid & 15;
    const int ty  = tid >> 4;
    const int m0  = blockIdx.y * 128;
    const int n0  = blockIdx.x * 128;

    float acc[8][8];
#pragma unroll
    for (int i = 0; i < 8; i++)
#pragma unroll
        for (int j = 0; j < 8; j++) acc[i][j] = 0.f;

    for (int kt = 0; kt < E_DIM; kt += 16) {
        // Load A tile (128x16) transposed into As
#pragma unroll
        for (int p = 0; p < 2; p++) {
            int f  = tid + p * 256;         // 0..511
            int r  = f >> 2;                // 0..127
            int c4 = (f & 3) << 2;          // 0,4,8,12
            float4 v = *(const float4*)(A + (size_t)(m0 + r) * E_DIM + kt + c4);
            As[c4 + 0][r] = v.x;
            As[c4 + 1][r] = v.y;
            As[c4 + 2][r] = v.z;
            As[c4 + 3][r] = v.w;
        }
        // Load B tile (16x128)
#pragma unroll
        for (int p = 0; p < 2; p++) {
            int f  = tid + p * 256;         // 0..511
            int r  = f >> 5;                // 0..15
            int c4 = (f & 31) << 2;         // 0..124
            *(float4*)(&Bs[r][c4]) =
                *(const float4*)(W + (size_t)(kt + r) * E_DIM + n0 + c4);
        }
        __syncthreads();

#pragma unroll
        for (int kk = 0; kk < 16; kk++) {
            float a[8], b[8];
            *(float4*)&a[0] = *(float4*)&As[kk][ty * 8];
            *(float4*)&a[4] = *(float4*)&As[kk][ty * 8 + 4];
            *(float4*)&b[0] = *(float4*)&Bs[kk][tx * 8];
            *(float4*)&b[4] = *(float4*)&Bs[kk][tx * 8 + 4];
#pragma unroll
            for (int i = 0; i < 8; i++)
#pragma unroll
                for (int j = 0; j < 8; j++)
                    acc[i][j] = fmaf(a[i], b[j], acc[i][j]);
        }
        __syncthreads();
    }

    // Epilogue: bias + scale
#pragma unroll
    for (int i = 0; i < 8; i++) {
        int m = m0 + ty * 8 + i;
#pragma unroll
        for (int j = 0; j < 8; j += 4) {
            int n = n0 + tx * 8 + j;
            float4 o;
            o.x = (acc[i][j + 0] + bias[n + 0]) * scale;
            o.y = (acc[i][j + 1] + bias[n + 1]) * scale;
            o.z = (acc[i][j + 2] + bias[n + 2]) * scale;
            o.w = (acc[i][j + 3] + bias[n + 3]) * scale;
            *(float4*)(C + (size_t)m * E_DIM + n) = o;
        }
    }
}

// ---------------------------------------------------------------------------
// Flash attention (fp32, online softmax).
// One CTA per (n, h, 64-query block). T tiled by 64. HD = 64.
// Smem layout (stride 68 floats = 272B, 16B aligned):
//   Qt [64][68]  d-major  Qt[d][qi]
//   Kt [64][68]  d-major  Kt[d][tj]
//   Pst[64][68]  Pst[tj][qi]   (P transposed)
//   Vs [64][68]  Vs[tj][d]
// Thread (ty,tx): score tile rows ty*4..+3 x cols tx*4..+3;
//                 O tile     rows ty*4..+3 x dims tx*4..+3.
// ---------------------------------------------------------------------------
#define SMS 68

__global__ __launch_bounds__(256, 2)
void flash_attn(const float* __restrict__ Q, const float* __restrict__ K,
                const float* __restrict__ V, float* __restrict__ O)
{
    extern __shared__ float sm[];
    float* Qt  = sm;
    float* Kt  = sm + 1 * 64 * SMS;
    float* Pst = sm + 2 * 64 * SMS;
    float* Vs  = sm + 3 * 64 * SMS;

    const int tid = threadIdx.x;
    const int tx  = tid & 15;
    const int ty  = tid >> 4;
    const int qb  = blockIdx.x;   // 0..31
    const int h   = blockIdx.y;   // 0..15
    const int n   = blockIdx.z;   // 0..1

    const float* Qbase = Q + (size_t)(n * S_LEN + qb * 64) * E_DIM + h * HD;
    const float* Kbase = K + (size_t)(n * T_LEN) * E_DIM + h * HD;
    const float* Vbase = V + (size_t)(n * T_LEN) * E_DIM + h * HD;

    // Load Q tile (64 x 64), store transposed (d-major)
#pragma unroll
    for (int p = 0; p < 4; p++) {
        int f  = tid + p * 256;   // 0..1023
        int r  = f >> 4;          // 0..63
        int d4 = (f & 15) << 2;   // 0..60
        float4 v = *(const float4*)(Qbase + (size_t)r * E_DIM + d4);
        Qt[(d4 + 0) * SMS + r] = v.x;
        Qt[(d4 + 1) * SMS + r] = v.y;
        Qt[(d4 + 2) * SMS + r] = v.z;
        Qt[(d4 + 3) * SMS + r] = v.w;
    }

    float o[4][4];
    float mrow[4], lrow[4];
#pragma unroll
    for (int i = 0; i < 4; i++) {
        mrow[i] = -1e30f;
        lrow[i] = 0.f;
#pragma unroll
        for (int c = 0; c < 4; c++) o[i][c] = 0.f;
    }

    for (int t0 = 0; t0 < T_LEN; t0 += 64) {
        // Load K (transposed) and V tiles
#pragma unroll
        for (int p = 0; p < 4; p++) {
            int f  = tid + p * 256;
            int r  = f >> 4;
            int d4 = (f & 15) << 2;
            float4 kv = *(const float4*)(Kbase + (size_t)(t0 + r) * E_DIM + d4);
            Kt[(d4 + 0) * SMS + r] = kv.x;
            Kt[(d4 + 1) * SMS + r] = kv.y;
            Kt[(d4 + 2) * SMS + r] = kv.z;
            Kt[(d4 + 3) * SMS + r] = kv.w;
            float4 vv = *(const float4*)(Vbase + (size_t)(t0 + r) * E_DIM + d4);
            *(float4*)(Vs + r * SMS + d4) = vv;
        }
        __syncthreads();   // (a) tiles visible; also covers Qt on first iter

        // S = Q K^T  (Q already pre-scaled by 1/sqrt(HD) in the projection)
        float s[4][4];
#pragma unroll
        for (int i = 0; i < 4; i++)
#pragma unroll
            for (int j = 0; j < 4; j++) s[i][j] = 0.f;

#pragma unroll 8
        for (int d = 0; d < 64; d++) {
            float4 qa = *(float4*)(Qt + d * SMS + ty * 4);
            float4 kb = *(float4*)(Kt + d * SMS + tx * 4);
            s[0][0] = fmaf(qa.x, kb.x, s[0][0]);
            s[0][1] = fmaf(qa.x, kb.y, s[0][1]);
            s[0][2] = fmaf(qa.x, kb.z, s[0][2]);
            s[0][3] = fmaf(qa.x, kb.w, s[0][3]);
            s[1][0] = fmaf(qa.y, kb.x, s[1][0]);
            s[1][1] = fmaf(qa.y, kb.y, s[1][1]);
            s[1][2] = fmaf(qa.y, kb.z, s[1][2]);
            s[1][3] = fmaf(qa.y, kb.w, s[1][3]);
            s[2][0] = fmaf(qa.z, kb.x, s[2][0]);
            s[2][1] = fmaf(qa.z, kb.y, s[2][1]);
            s[2][2] = fmaf(qa.z, kb.z, s[2][2]);
            s[2][3] = fmaf(qa.z, kb.w, s[2][3]);
            s[3][0] = fmaf(qa.w, kb.x, s[3][0]);
            s[3][1] = fmaf(qa.w, kb.y, s[3][1]);
            s[3][2] = fmaf(qa.w, kb.z, s[3][2]);
            s[3][3] = fmaf(qa.w, kb.w, s[3][3]);
        }

        // Online softmax update (row groups = 16 lanes sharing ty)
#pragma unroll
        for (int i = 0; i < 4; i++) {
            float mx = fmaxf(fmaxf(s[i][0], s[i][1]), fmaxf(s[i][2], s[i][3]));
            mx = fmaxf(mx, __shfl_xor_sync(0xffffffffu, mx, 8));
            mx = fmaxf(mx, __shfl_xor_sync(0xffffffffu, mx, 4));
            mx = fmaxf(mx, __shfl_xor_sync(0xffffffffu, mx, 2));
            mx = fmaxf(mx, __shfl_xor_sync(0xffffffffu, mx, 1));
            float mnew  = fmaxf(mrow[i], mx);
            float alpha = __expf(mrow[i] - mnew);
            float ls = 0.f;
#pragma unroll
            for (int j = 0; j < 4; j++) {
                float p = __expf(s[i][j] - mnew);
                s[i][j] = p;
                ls += p;
            }
            ls += __shfl_xor_sync(0xffffffffu, ls, 8);
            ls += __shfl_xor_sync(0xffffffffu, ls, 4);
            ls += __shfl_xor_sync(0xffffffffu, ls, 2);
            ls += __shfl_xor_sync(0xffffffffu, ls, 1);
            lrow[i] = lrow[i] * alpha + ls;
            mrow[i] = mnew;
#pragma unroll
            for (int c = 0; c < 4; c++) o[i][c] *= alpha;
        }

        // Stage P transposed: Pst[tj][qi]
#pragma unroll
        for (int j = 0; j < 4; j++)
#pragma unroll
            for (int i = 0; i < 4; i++)
                Pst[(tx * 4 + j) * SMS + ty * 4 + i] = s[i][j];
        __syncthreads();   // (b) P visible

        // O += P V
#pragma unroll 8
        for (int j = 0; j < 64; j++) {
            float4 pv = *(float4*)(Pst + j * SMS + ty * 4);
            float4 vv = *(float4*)(Vs  + j * SMS + tx * 4);
            o[0][0] = fmaf(pv.x, vv.x, o[0][0]);
            o[0][1] = fmaf(pv.x, vv.y, o[0][1]);
            o[0][2] = fmaf(pv.x, vv.z, o[0][2]);
            o[0][3] = fmaf(pv.x, vv.w, o[0][3]);
            o[1][0] = fmaf(pv.y, vv.x, o[1][0]);
            o[1][1] = fmaf(pv.y, vv.y, o[1][1]);
            o[1][2] = fmaf(pv.y, vv.z, o[1][2]);
            o[1][3] = fmaf(pv.y, vv.w, o[1][3]);
            o[2][0] = fmaf(pv.z, vv.x, o[2][0]);
            o[2][1] = fmaf(pv.z, vv.y, o[2][1]);
            o[2][2] = fmaf(pv.z, vv.z, o[2][2]);
            o[2][3] = fmaf(pv.z, vv.w, o[2][3]);
            o[3][0] = fmaf(pv.w, vv.x, o[3][0]);
            o[3][1] = fmaf(pv.w, vv.y, o[3][1]);
            o[3][2] = fmaf(pv.w, vv.z, o[3][2]);
            o[3][3] = fmaf(pv.w, vv.w, o[3][3]);
        }
        __syncthreads();   // (c) end of iter: all smem reads done
    }

    // Normalize and write to [N,S,E] layout
#pragma unroll
    for (int i = 0; i < 4; i++) {
        float inv = 1.f / lrow[i];
        float4 ov;
        ov.x = o[i][0] * inv;
        ov.y = o[i][1] * inv;
        ov.z = o[i][2] * inv;
        ov.w = o[i][3] * inv;
        int row = n * S_LEN + qb * 64 + ty * 4 + i;
        *(float4*)(O + (size_t)row * E_DIM + h * HD + tx * 4) = ov;
    }
}

// ---------------------------------------------------------------------------
// Launch
// ---------------------------------------------------------------------------
extern "C" void kernel_launch(void* const* d_in, const int* in_sizes, int n_in,
                              void* d_out, int out_size)
{
    const float* query = (const float*)d_in[0];
    const float* key   = (const float*)d_in[1];
    const float* value = (const float*)d_in[2];
    const float* Wq    = (const float*)d_in[3];
    const float* bq    = (const float*)d_in[4];
    const float* Wk    = (const float*)d_in[5];
    const float* bk    = (const float*)d_in[6];
    const float* Wv    = (const float*)d_in[7];
    const float* bv    = (const float*)d_in[8];
    const float* Wo    = (const float*)d_in[9];
    const float* bo    = (const float*)d_in[10];
    float* out = (float*)d_out;

    float *q_p, *k_p, *v_p, *ao_p;
    cudaGetSymbolAddress((void**)&q_p,  g_q);
    cudaGetSymbolAddress((void**)&k_p,  g_k);
    cudaGetSymbolAddress((void**)&v_p,  g_v);
    cudaGetSymbolAddress((void**)&ao_p, g_ao);

    dim3 gemm_grid(E_DIM / 128, M_ROWS / 128);   // 8 x 32

    // Q projection pre-scaled by 1/sqrt(HD) = 0.125 (bias included, matching ref)
    gemm_bias<<<gemm_grid, 256>>>(query, Wq, bq, q_p, 0.125f);
    gemm_bias<<<gemm_grid, 256>>>(key,   Wk, bk, k_p, 1.0f);
    gemm_bias<<<gemm_grid, 256>>>(value, Wv, bv, v_p, 1.0f);

    int smem_bytes = 4 * 64 * SMS * (int)sizeof(float);   // 69632
    cudaFuncSetAttribute(flash_attn,
                         cudaFuncAttributeMaxDynamicSharedMemorySize, smem_bytes);
    dim3 attn_grid(S_LEN / 64, H_NUM, N_B);               // 32 x 16 x 2
    flash_attn<<<attn_grid, 256, smem_bytes>>>(q_p, k_p, v_p, ao_p);

    gemm_bias<<<gemm_grid, 256>>>(ao_p, Wo, bo, out, 1.0f);
}

// round 3
// speedup vs baseline: 3.1161x; 3.1161x over previous
#include <cuda_runtime.h>
#include <math.h>

// Problem constants
#define N_B    2
#define S_LEN  2048
#define T_LEN  2048
#define E_DIM  1024
#define H_NUM  16
#define HD     64
#define M_ROWS (N_B * S_LEN)   // 4096

// Scratch (device globals -> no runtime allocation)
__device__ float g_q [M_ROWS * E_DIM];
__device__ float g_k [M_ROWS * E_DIM];
__device__ float g_v [M_ROWS * E_DIM];
__device__ float g_ao[M_ROWS * E_DIM];

// ---------------------------------------------------------------------------
// tf32 helpers
// ---------------------------------------------------------------------------
__device__ __forceinline__ unsigned f2tf32(float f) {
    unsigned u;
    asm("cvt.rna.tf32.f32 %0, %1;" : "=r"(u) : "f"(f));
    return u;
}

// D = A(16x8, tf32, row) * B(8x8, tf32, col) + C  (fp32 accum, in-place)
__device__ __forceinline__ void mma_tf32(float* c, const unsigned* a, const unsigned* b) {
    asm volatile(
        "mma.sync.aligned.m16n8k8.row.col.f32.tf32.tf32.f32 "
        "{%0,%1,%2,%3}, {%4,%5,%6,%7}, {%8,%9}, {%0,%1,%2,%3};"
        : "+f"(c[0]), "+f"(c[1]), "+f"(c[2]), "+f"(c[3])
        : "r"(a[0]), "r"(a[1]), "r"(a[2]), "r"(a[3]), "r"(b[0]), "r"(b[1]));
}

// ---------------------------------------------------------------------------
// GEMM (tf32 tensor core): C[M,1024] = (A[M,1024] @ W[1024,1024] + bias)*scale
// 128x128 CTA tile, BK=32, 256 threads = 8 warps (2x4), warp tile 64x32.
// ---------------------------------------------------------------------------
#define ASTR 36
#define BSTR 136

__global__ __launch_bounds__(256, 2)
void gemm_tc(const float* __restrict__ A, const float* __restrict__ W,
             const float* __restrict__ bias, float* __restrict__ C,
             float scale)
{
    __shared__ unsigned As[128 * ASTR];   // As[m][k], k contiguous, pad 36
    __shared__ unsigned Bs[32 * BSTR];    // Bs[k][n], n contiguous, pad 136

    const int tid  = threadIdx.x;
    const int lane = tid & 31;
    const int w    = tid >> 5;
    const int wm   = (w >> 2) * 64;      // warp row offset
    const int wn   = (w & 3) * 32;       // warp col offset
    const int m0   = blockIdx.y * 128;
    const int n0   = blockIdx.x * 128;

    float acc[4][4][4];                  // [mi][ni][c]
#pragma unroll
    for (int mi = 0; mi < 4; mi++)
#pragma unroll
        for (int ni = 0; ni < 4; ni++)
#pragma unroll
            for (int c = 0; c < 4; c++) acc[mi][ni][c] = 0.f;

    for (int kt = 0; kt < E_DIM; kt += 32) {
        // A tile 128x32
#pragma unroll
        for (int p = 0; p < 4; p++) {
            int f = tid + p * 256;            // 0..1023
            int r = f >> 3;                   // 0..127
            int c = (f & 7) << 2;             // 0..28
            float4 v = *(const float4*)(A + (size_t)(m0 + r) * E_DIM + kt + c);
            As[r * ASTR + c + 0] = f2tf32(v.x);
            As[r * ASTR + c + 1] = f2tf32(v.y);
            As[r * ASTR + c + 2] = f2tf32(v.z);
            As[r * ASTR + c + 3] = f2tf32(v.w);
        }
        // B tile 32x128
#pragma unroll
        for (int p = 0; p < 4; p++) {
            int f = tid + p * 256;
            int r = f >> 5;                   // 0..31
            int c = (f & 31) << 2;            // 0..124
            float4 v = *(const float4*)(W + (size_t)(kt + r) * E_DIM + n0 + c);
            Bs[r * BSTR + c + 0] = f2tf32(v.x);
            Bs[r * BSTR + c + 1] = f2tf32(v.y);
            Bs[r * BSTR + c + 2] = f2tf32(v.z);
            Bs[r * BSTR + c + 3] = f2tf32(v.w);
        }
        __syncthreads();

#pragma unroll
        for (int kk = 0; kk < 4; kk++) {
            const int kb = kk * 8;
            unsigned af[4][4];
#pragma unroll
            for (int mi = 0; mi < 4; mi++) {
                int rbase = wm + mi * 16 + (lane >> 2);
                int cbase = kb + (lane & 3);
                af[mi][0] = As[rbase * ASTR + cbase];
                af[mi][1] = As[(rbase + 8) * ASTR + cbase];
                af[mi][2] = As[rbase * ASTR + cbase + 4];
                af[mi][3] = As[(rbase + 8) * ASTR + cbase + 4];
            }
            unsigned bf[4][2];
#pragma unroll
            for (int ni = 0; ni < 4; ni++) {
                int kbase = kb + (lane & 3);
                int nbase = wn + ni * 8 + (lane >> 2);
                bf[ni][0] = Bs[kbase * BSTR + nbase];
                bf[ni][1] = Bs[(kbase + 4) * BSTR + nbase];
            }
#pragma unroll
            for (int mi = 0; mi < 4; mi++)
#pragma unroll
                for (int ni = 0; ni < 4; ni++)
                    mma_tf32(acc[mi][ni], af[mi], bf[ni]);
        }
        __syncthreads();
    }

    // Epilogue
#pragma unroll
    for (int mi = 0; mi < 4; mi++) {
#pragma unroll
        for (int ni = 0; ni < 4; ni++) {
            int row = m0 + wm + mi * 16 + (lane >> 2);
            int col = n0 + wn + ni * 8 + 2 * (lane & 3);
            float2 o0, o1;
            o0.x = (acc[mi][ni][0] + bias[col])     * scale;
            o0.y = (acc[mi][ni][1] + bias[col + 1]) * scale;
            o1.x = (acc[mi][ni][2] + bias[col])     * scale;
            o1.y = (acc[mi][ni][3] + bias[col + 1]) * scale;
            *(float2*)(C + (size_t)row * E_DIM + col)       = o0;
            *(float2*)(C + (size_t)(row + 8) * E_DIM + col) = o1;
        }
    }
}

// ---------------------------------------------------------------------------
// Flash attention, tf32 tensor core.
// CTA = 128 threads (4 warps) per (n, h, 64-query block). T tiled by 64.
// Warp w owns score/O rows 16w..16w+15.
// Smem (all tf32-as-uint):
//   Qs[64][68]  [q][d]   Ks[64][68] [t][d]   Ps[64][68] [q][t]   Vs[64][72] [t][d]
// ---------------------------------------------------------------------------
#define QSTR 68
#define VSTR 72
#define SM_Q  0
#define SM_K  (64 * QSTR)
#define SM_P  (2 * 64 * QSTR)
#define SM_V  (3 * 64 * QSTR)
#define SM_TOT (3 * 64 * QSTR + 64 * VSTR)   // 17664 uints = 70656 B

__global__ __launch_bounds__(128, 2)
void flash_attn_tc(const float* __restrict__ Q, const float* __restrict__ K,
                   const float* __restrict__ V, float* __restrict__ O)
{
    extern __shared__ unsigned sm[];
    unsigned* Qs = sm + SM_Q;
    unsigned* Ks = sm + SM_K;
    unsigned* Ps = sm + SM_P;
    unsigned* Vs = sm + SM_V;

    const int tid  = threadIdx.x;
    const int lane = tid & 31;
    const int w    = tid >> 5;
    const int qb   = blockIdx.x;
    const int h    = blockIdx.y;
    const int n    = blockIdx.z;

    const int qr   = (lane >> 2);    // 0..7
    const int qc   = (lane & 3);     // 0..3

    const float* Qbase = Q + (size_t)(n * S_LEN + qb * 64) * E_DIM + h * HD;
    const float* Kbase = K + (size_t)(n * T_LEN) * E_DIM + h * HD;
    const float* Vbase = V + (size_t)(n * T_LEN) * E_DIM + h * HD;

    // Load Q tile (64x64), convert to tf32
#pragma unroll
    for (int p = 0; p < 8; p++) {
        int f = tid + p * 128;        // 0..1023
        int r = f >> 4;               // 0..63
        int c = (f & 15) << 2;        // 0..60
        float4 v = *(const float4*)(Qbase + (size_t)r * E_DIM + c);
        Qs[r * QSTR + c + 0] = f2tf32(v.x);
        Qs[r * QSTR + c + 1] = f2tf32(v.y);
        Qs[r * QSTR + c + 2] = f2tf32(v.z);
        Qs[r * QSTR + c + 3] = f2tf32(v.w);
    }

    float oacc[8][4];
#pragma unroll
    for (int nt = 0; nt < 8; nt++)
#pragma unroll
        for (int c = 0; c < 4; c++) oacc[nt][c] = 0.f;
    float mr0 = -1e30f, mr1 = -1e30f, lr0 = 0.f, lr1 = 0.f;

    for (int t0 = 0; t0 < T_LEN; t0 += 64) {
        // Load K and V tiles
#pragma unroll
        for (int p = 0; p < 8; p++) {
            int f = tid + p * 128;
            int r = f >> 4;
            int c = (f & 15) << 2;
            float4 kv = *(const float4*)(Kbase + (size_t)(t0 + r) * E_DIM + c);
            Ks[r * QSTR + c + 0] = f2tf32(kv.x);
            Ks[r * QSTR + c + 1] = f2tf32(kv.y);
            Ks[r * QSTR + c + 2] = f2tf32(kv.z);
            Ks[r * QSTR + c + 3] = f2tf32(kv.w);
            float4 vv = *(const float4*)(Vbase + (size_t)(t0 + r) * E_DIM + c);
            Vs[r * VSTR + c + 0] = f2tf32(vv.x);
            Vs[r * VSTR + c + 1] = f2tf32(vv.y);
            Vs[r * VSTR + c + 2] = f2tf32(vv.z);
            Vs[r * VSTR + c + 3] = f2tf32(vv.w);
        }
        __syncthreads();

        // S = Q * K^T   (Q pre-scaled by 1/sqrt(HD) in the projection)
        float sacc[8][4];
#pragma unroll
        for (int nt = 0; nt < 8; nt++)
#pragma unroll
            for (int c = 0; c < 4; c++) sacc[nt][c] = 0.f;

#pragma unroll
        for (int kk = 0; kk < 8; kk++) {
            const int kb = kk * 8;
            unsigned a[4];
            int rbase = (w * 16 + qr) * QSTR + kb + qc;
            a[0] = Qs[rbase];
            a[1] = Qs[rbase + 8 * QSTR];
            a[2] = Qs[rbase + 4];
            a[3] = Qs[rbase + 8 * QSTR + 4];
#pragma unroll
            for (int nt = 0; nt < 8; nt++) {
                unsigned b[2];
                int bi = (nt * 8 + qr) * QSTR + kb + qc;
                b[0] = Ks[bi];
                b[1] = Ks[bi + 4];
                mma_tf32(sacc[nt], a, b);
            }
        }

        // Online softmax: thread owns rows r0 = w*16+qr (c0,c1) and r0+8 (c2,c3)
        float mx0 = -1e30f, mx1 = -1e30f;
#pragma unroll
        for (int nt = 0; nt < 8; nt++) {
            mx0 = fmaxf(mx0, fmaxf(sacc[nt][0], sacc[nt][1]));
            mx1 = fmaxf(mx1, fmaxf(sacc[nt][2], sacc[nt][3]));
        }
        mx0 = fmaxf(mx0, __shfl_xor_sync(0xffffffffu, mx0, 1));
        mx0 = fmaxf(mx0, __shfl_xor_sync(0xffffffffu, mx0, 2));
        mx1 = fmaxf(mx1, __shfl_xor_sync(0xffffffffu, mx1, 1));
        mx1 = fmaxf(mx1, __shfl_xor_sync(0xffffffffu, mx1, 2));

        float mn0 = fmaxf(mr0, mx0);
        float mn1 = fmaxf(mr1, mx1);
        float al0 = __expf(mr0 - mn0);
        float al1 = __expf(mr1 - mn1);
        mr0 = mn0;
        mr1 = mn1;

        float ls0 = 0.f, ls1 = 0.f;
        int prow0 = (w * 16 + qr) * QSTR + 2 * qc;
        int prow1 = prow0 + 8 * QSTR;
#pragma unroll
        for (int nt = 0; nt < 8; nt++) {
            float p00 = __expf(sacc[nt][0] - mn0);
            float p01 = __expf(sacc[nt][1] - mn0);
            float p10 = __expf(sacc[nt][2] - mn1);
            float p11 = __expf(sacc[nt][3] - mn1);
            ls0 += p00 + p01;
            ls1 += p10 + p11;
            Ps[prow0 + nt * 8]     = f2tf32(p00);
            Ps[prow0 + nt * 8 + 1] = f2tf32(p01);
            Ps[prow1 + nt * 8]     = f2tf32(p10);
            Ps[prow1 + nt * 8 + 1] = f2tf32(p11);
            oacc[nt][0] *= al0;
            oacc[nt][1] *= al0;
            oacc[nt][2] *= al1;
            oacc[nt][3] *= al1;
        }
        ls0 += __shfl_xor_sync(0xffffffffu, ls0, 1);
        ls0 += __shfl_xor_sync(0xffffffffu, ls0, 2);
        ls1 += __shfl_xor_sync(0xffffffffu, ls1, 1);
        ls1 += __shfl_xor_sync(0xffffffffu, ls1, 2);
        lr0 = lr0 * al0 + ls0;
        lr1 = lr1 * al1 + ls1;

        __syncwarp();   // P rows of this warp visible warp-wide

        // O += P * V   (m=q16, k=t, n=d)
#pragma unroll
        for (int kk = 0; kk < 8; kk++) {
            const int kb = kk * 8;
            unsigned a[4];
            int rbase = (w * 16 + qr) * QSTR + kb + qc;
            a[0] = Ps[rbase];
            a[1] = Ps[rbase + 8 * QSTR];
            a[2] = Ps[rbase + 4];
            a[3] = Ps[rbase + 8 * QSTR + 4];
#pragma unroll
            for (int nt = 0; nt < 8; nt++) {
                unsigned b[2];
                int bi = (kb + qc) * VSTR + nt * 8 + qr;
                b[0] = Vs[bi];
                b[1] = Vs[bi + 4 * VSTR];
                mma_tf32(oacc[nt], a, b);
            }
        }
        __syncthreads();   // Ks/Vs consumed; safe to overwrite next iter
    }

    // Normalize and write out: O[n*S + qb*64 + row][h*64 + col]
    float inv0 = 1.f / lr0;
    float inv1 = 1.f / lr1;
    int grow0 = n * S_LEN + qb * 64 + w * 16 + qr;
    int gcol  = h * HD + 2 * qc;
#pragma unroll
    for (int nt = 0; nt < 8; nt++) {
        float2 o0, o1;
        o0.x = oacc[nt][0] * inv0;
        o0.y = oacc[nt][1] * inv0;
        o1.x = oacc[nt][2] * inv1;
        o1.y = oacc[nt][3] * inv1;
        *(float2*)(O + (size_t)grow0 * E_DIM + gcol + nt * 8)       = o0;
        *(float2*)(O + (size_t)(grow0 + 8) * E_DIM + gcol + nt * 8) = o1;
    }
}

// ---------------------------------------------------------------------------
// Launch
// ---------------------------------------------------------------------------
extern "C" void kernel_launch(void* const* d_in, const int* in_sizes, int n_in,
                              void* d_out, int out_size)
{
    const float* query = (const float*)d_in[0];
    const float* key   = (const float*)d_in[1];
    const float* value = (const float*)d_in[2];
    const float* Wq    = (const float*)d_in[3];
    const float* bq    = (const float*)d_in[4];
    const float* Wk    = (const float*)d_in[5];
    const float* bk    = (const float*)d_in[6];
    const float* Wv    = (const float*)d_in[7];
    const float* bv    = (const float*)d_in[8];
    const float* Wo    = (const float*)d_in[9];
    const float* bo    = (const float*)d_in[10];
    float* out = (float*)d_out;

    float *q_p, *k_p, *v_p, *ao_p;
    cudaGetSymbolAddress((void**)&q_p,  g_q);
    cudaGetSymbolAddress((void**)&k_p,  g_k);
    cudaGetSymbolAddress((void**)&v_p,  g_v);
    cudaGetSymbolAddress((void**)&ao_p, g_ao);

    dim3 gemm_grid(E_DIM / 128, M_ROWS / 128);   // 8 x 32

    // Q projection pre-scaled by 1/sqrt(HD) = 0.125
    gemm_tc<<<gemm_grid, 256>>>(query, Wq, bq, q_p, 0.125f);
    gemm_tc<<<gemm_grid, 256>>>(key,   Wk, bk, k_p, 1.0f);
    gemm_tc<<<gemm_grid, 256>>>(value, Wv, bv, v_p, 1.0f);

    int smem_bytes = SM_TOT * (int)sizeof(unsigned);   // 70656
    cudaFuncSetAttribute(flash_attn_tc,
                         cudaFuncAttributeMaxDynamicSharedMemorySize, smem_bytes);
    dim3 attn_grid(S_LEN / 64, H_NUM, N_B);            // 32 x 16 x 2
    flash_attn_tc<<<attn_grid, 128, smem_bytes>>>(q_p, k_p, v_p, ao_p);

    gemm_tc<<<gemm_grid, 256>>>(ao_p, Wo, bo, out, 1.0f);
}